// round 17
// baseline (speedup 1.0000x reference)
#include <cuda_runtime.h>
#include <cuda_bf16.h>
#include <stdint.h>
#include <math.h>

// Problem constants
#define H   24
#define Nn  3072
#define D   128
#define BMQ 192
#define G   16
#define HG  (H * G)
#define TOPK 896

// ---------------- device scratch (static; no runtime allocation) -------------
__device__ float g_S[(size_t)H * Nn * Nn];       // S (fp32)
__device__ __nv_bfloat16 g_ph[(size_t)H * Nn * Nn];  // P hi plane
__device__ __nv_bfloat16 g_pl[(size_t)H * Nn * Nn];  // P lo plane
__device__ float g_cs[HG * Nn];
__device__ uint32_t g_mask[HG * 96];             // per-group column bitmask
// 3-way split planes for Q and K (a + b + c, each bf16)
__device__ __nv_bfloat16 g_qa[(size_t)H * Nn * D];
__device__ __nv_bfloat16 g_qb[(size_t)H * Nn * D];
__device__ __nv_bfloat16 g_qc[(size_t)H * Nn * D];
__device__ __nv_bfloat16 g_ka[(size_t)H * Nn * D];
__device__ __nv_bfloat16 g_kb[(size_t)H * Nn * D];
__device__ __nv_bfloat16 g_kc[(size_t)H * Nn * D];
// 2-way split V^T planes [h][d][k]
__device__ __nv_bfloat16 g_vth[(size_t)H * D * Nn];
__device__ __nv_bfloat16 g_vtl[(size_t)H * D * Nn];

// ---------------- helpers ----------------------------------------------------
__device__ __forceinline__ uint32_t smem_to_u32(const void* p) {
    uint32_t a;
    asm("{ .reg .u64 t; cvta.to.shared.u64 t, %1; cvt.u32.u64 %0, t; }" : "=r"(a) : "l"(p));
    return a;
}

__device__ __forceinline__ void ldsm_x4(uint32_t& r0, uint32_t& r1, uint32_t& r2,
                                        uint32_t& r3, uint32_t addr) {
    asm volatile("ldmatrix.sync.aligned.m8n8.x4.shared.b16 {%0,%1,%2,%3}, [%4];"
                 : "=r"(r0), "=r"(r1), "=r"(r2), "=r"(r3) : "r"(addr));
}

__device__ __forceinline__ void mma_bf16(float* c, const uint32_t* a, const uint32_t* b) {
    asm volatile(
        "mma.sync.aligned.m16n8k16.row.col.f32.bf16.bf16.f32 "
        "{%0,%1,%2,%3}, {%4,%5,%6,%7}, {%8,%9}, {%0,%1,%2,%3};"
        : "+f"(c[0]), "+f"(c[1]), "+f"(c[2]), "+f"(c[3])
        : "r"(a[0]), "r"(a[1]), "r"(a[2]), "r"(a[3]), "r"(b[0]), "r"(b[1]));
}

// smem tile: 128 rows x 256B (128 bf16), 16B chunks xor-swizzled by row%8
__device__ __forceinline__ uint32_t sw_off(int row, int c16) {
    return (uint32_t)(row * 256 + ((c16 ^ (row & 7)) << 4));
}

#define PLANE 32768

// ---------------- threefry2x32 ----------------------------------------------
#define TF_ROUND(x0, x1, r) { x0 += x1; x1 = (x1 << r) | (x1 >> (32 - r)); x1 ^= x0; }
__device__ __forceinline__ uint2 tf2x32(unsigned k0, unsigned k1, unsigned c0, unsigned c1) {
    unsigned ks2 = k0 ^ k1 ^ 0x1BD11BDAu;
    unsigned x0 = c0 + k0, x1 = c1 + k1;
    TF_ROUND(x0, x1, 13) TF_ROUND(x0, x1, 15) TF_ROUND(x0, x1, 26) TF_ROUND(x0, x1, 6)
    x0 += k1;  x1 += ks2 + 1u;
    TF_ROUND(x0, x1, 17) TF_ROUND(x0, x1, 29) TF_ROUND(x0, x1, 16) TF_ROUND(x0, x1, 24)
    x0 += ks2; x1 += k0 + 2u;
    TF_ROUND(x0, x1, 13) TF_ROUND(x0, x1, 15) TF_ROUND(x0, x1, 26) TF_ROUND(x0, x1, 6)
    x0 += k0;  x1 += k1 + 3u;
    TF_ROUND(x0, x1, 17) TF_ROUND(x0, x1, 29) TF_ROUND(x0, x1, 16) TF_ROUND(x0, x1, 24)
    x0 += k1;  x1 += ks2 + 4u;
    TF_ROUND(x0, x1, 13) TF_ROUND(x0, x1, 15) TF_ROUND(x0, x1, 26) TF_ROUND(x0, x1, 6)
    x0 += ks2; x1 += k0 + 5u;
    return make_uint2(x0, x1);
}
__device__ __forceinline__ unsigned tf_bits32(unsigned k0, unsigned k1, unsigned f) {
    uint2 o = tf2x32(k0, k1, 0u, f);
    return o.x ^ o.y;
}

// =============================================================================
// K0a: split q,k into 3 bf16 planes (a + b + c); also zero g_cs
// =============================================================================
__global__ __launch_bounds__(256) void split_qk_kernel(const float* __restrict__ q,
                                                       const float* __restrict__ k) {
    const int which = blockIdx.y;
    if (which == 0 && blockIdx.x < 4608)
        g_cs[blockIdx.x * 256 + threadIdx.x] = 0.f;
    const float* src = which ? k : q;
    __nv_bfloat16* da = which ? g_ka : g_qa;
    __nv_bfloat16* db = which ? g_kb : g_qb;
    __nv_bfloat16* dc = which ? g_kc : g_qc;
    size_t i = (size_t)blockIdx.x * 256 + threadIdx.x;   // float4 index
    float4 x = reinterpret_cast<const float4*>(src)[i];
    float v[4] = {x.x, x.y, x.z, x.w};
    unsigned short as_[4], bs[4], cs_[4];
#pragma unroll
    for (int j = 0; j < 4; j++) {
        __nv_bfloat16 ab = __float2bfloat16_rn(v[j]);
        float r1 = v[j] - __bfloat162float(ab);
        __nv_bfloat16 bb = __float2bfloat16_rn(r1);
        float r2 = r1 - __bfloat162float(bb);
        __nv_bfloat16 cb = __float2bfloat16_rn(r2);
        as_[j] = __bfloat16_as_ushort(ab);
        bs[j]  = __bfloat16_as_ushort(bb);
        cs_[j] = __bfloat16_as_ushort(cb);
    }
    uint2 av, bv, cv;
    av.x = (uint32_t)as_[0] | ((uint32_t)as_[1] << 16);
    av.y = (uint32_t)as_[2] | ((uint32_t)as_[3] << 16);
    bv.x = (uint32_t)bs[0]  | ((uint32_t)bs[1] << 16);
    bv.y = (uint32_t)bs[2]  | ((uint32_t)bs[3] << 16);
    cv.x = (uint32_t)cs_[0] | ((uint32_t)cs_[1] << 16);
    cv.y = (uint32_t)cs_[2] | ((uint32_t)cs_[3] << 16);
    reinterpret_cast<uint2*>(da)[i] = av;
    reinterpret_cast<uint2*>(db)[i] = bv;
    reinterpret_cast<uint2*>(dc)[i] = cv;
}

// =============================================================================
// K0b: transpose + split V -> VT hi/lo planes [h][d][k]
// =============================================================================
__global__ void vtrans_kernel(const float* __restrict__ v) {
    const int h = blockIdx.z, k0 = blockIdx.x * 32, d0 = blockIdx.y * 32;
    __shared__ float tile[32][33];
    const int tx = threadIdx.x, ty = threadIdx.y;
    const float* V = v + (size_t)h * Nn * D;
    for (int r = ty; r < 32; r += 8)
        tile[r][tx] = V[(size_t)(k0 + r) * D + d0 + tx];
    __syncthreads();
    for (int r = ty; r < 32; r += 8) {
        float val = tile[tx][r];
        __nv_bfloat16 hb = __float2bfloat16_rn(val);
        float rem = val - __bfloat162float(hb);
        __nv_bfloat16 lb = __float2bfloat16_rn(rem);
        size_t o = (size_t)h * D * Nn + (size_t)(d0 + r) * Nn + k0 + tx;
        g_vth[o] = hb;
        g_vtl[o] = lb;
    }
}

// =============================================================================
// K1: S = scale * Q K^T via mma.sync bf16, 3-way split (6 products)
//     256 threads, 8 warps, warp tile 64(m) x 32(n); A planes register-cached
// =============================================================================
__global__ __launch_bounds__(256) void qk_mma_kernel() {
    extern __shared__ char smem[];
    const uint32_t sb = smem_to_u32(smem);
    const int t = threadIdx.x, lane = t & 31, wid = t >> 5;
    const int h = blockIdx.z, bm = blockIdx.x * 128, bn = blockIdx.y * 128;

    {   // fill 6 planes
        const size_t qg = (size_t)h * Nn * D + (size_t)bm * D;
        const size_t kg = (size_t)h * Nn * D + (size_t)bn * D;
        const __nv_bfloat16* s0 = g_qa + qg;
        const __nv_bfloat16* s1 = g_qb + qg;
        const __nv_bfloat16* s2 = g_qc + qg;
        const __nv_bfloat16* s3 = g_ka + kg;
        const __nv_bfloat16* s4 = g_kb + kg;
        const __nv_bfloat16* s5 = g_kc + kg;
        for (int i = t; i < 2048; i += 256) {
            int row = i >> 4, c16 = i & 15;
            uint32_t o = sw_off(row, c16);
            size_t g = (size_t)row * D + c16 * 8;
            *reinterpret_cast<uint4*>(smem + o)             = *reinterpret_cast<const uint4*>(s0 + g);
            *reinterpret_cast<uint4*>(smem + PLANE + o)     = *reinterpret_cast<const uint4*>(s1 + g);
            *reinterpret_cast<uint4*>(smem + 2 * PLANE + o) = *reinterpret_cast<const uint4*>(s2 + g);
            *reinterpret_cast<uint4*>(smem + 3 * PLANE + o) = *reinterpret_cast<const uint4*>(s3 + g);
            *reinterpret_cast<uint4*>(smem + 4 * PLANE + o) = *reinterpret_cast<const uint4*>(s4 + g);
            *reinterpret_cast<uint4*>(smem + 5 * PLANE + o) = *reinterpret_cast<const uint4*>(s5 + g);
        }
    }
    __syncthreads();

    const int m0 = (wid >> 2) * 64, n0 = (wid & 3) * 32;
    float acc[4][4][4];
#pragma unroll
    for (int i = 0; i < 4; i++)
#pragma unroll
        for (int j = 0; j < 4; j++)
#pragma unroll
            for (int c = 0; c < 4; c++) acc[i][j][c] = 0.f;

#pragma unroll
    for (int kk = 0; kk < 8; kk++) {
        const int arow = (lane & 15), ach = kk * 2 + (lane >> 4);
        uint32_t A[3][4][4];
#pragma unroll
        for (int ai = 0; ai < 3; ai++)
#pragma unroll
            for (int mi = 0; mi < 4; mi++)
                ldsm_x4(A[ai][mi][0], A[ai][mi][1], A[ai][mi][2], A[ai][mi][3],
                        sb + ai * PLANE + sw_off(m0 + mi * 16 + arow, ach));
#pragma unroll
        for (int bi = 0; bi < 3; bi++) {
            uint32_t B[4][2];
#pragma unroll
            for (int nj = 0; nj < 2; nj++) {
                int row = n0 + nj * 16 + arow;
                uint32_t r0, r1, r2, r3;
                ldsm_x4(r0, r1, r2, r3, sb + (3 + bi) * PLANE + sw_off(row, ach));
                B[nj * 2][0] = r0; B[nj * 2][1] = r2;
                B[nj * 2 + 1][0] = r1; B[nj * 2 + 1][1] = r3;
            }
            const int nA = 3 - bi;   // Ka:{Qa,Qb,Qc} Kb:{Qa,Qb} Kc:{Qa}
#pragma unroll
            for (int ai = 0; ai < 3; ai++) {
                if (ai >= nA) continue;
#pragma unroll
                for (int mi = 0; mi < 4; mi++)
#pragma unroll
                    for (int n8 = 0; n8 < 4; n8++)
                        mma_bf16(acc[mi][n8], A[ai][mi], B[n8]);
            }
        }
    }

    const float scale = 0.08838834764831845f;
    float* S = g_S + (size_t)h * Nn * Nn;
#pragma unroll
    for (int mi = 0; mi < 4; mi++) {
#pragma unroll
        for (int n8 = 0; n8 < 4; n8++) {
            int r = bm + m0 + mi * 16 + (lane >> 2);
            int c = bn + n0 + n8 * 8 + (lane & 3) * 2;
            float2 v01 = make_float2(acc[mi][n8][0] * scale, acc[mi][n8][1] * scale);
            float2 v23 = make_float2(acc[mi][n8][2] * scale, acc[mi][n8][3] * scale);
            *reinterpret_cast<float2*>(&S[(size_t)r * Nn + c]) = v01;
            *reinterpret_cast<float2*>(&S[(size_t)(r + 8) * Nn + c]) = v23;
        }
    }
}

// =============================================================================
// K2: fused row softmax + group column sums; P written as bf16 hi/lo planes
//     grid (4G, H): each CTA does 48 rows of one group; partial cs via atomics
// =============================================================================
__global__ __launch_bounds__(256) void softmax_cs_kernel() {
    const int g = blockIdx.x >> 2, quarter = blockIdx.x & 3, h = blockIdx.y;
    const int t = threadIdx.x, lane = t & 31, warp = t >> 5;

    __shared__ float colsum[Nn];
    __shared__ float redm[8];
    __shared__ float reds[8];

    for (int j = t; j < Nn; j += 256) colsum[j] = 0.f;
    __syncthreads();

    const int r0 = quarter * 48;
    for (int r = r0; r < r0 + 48; r++) {
        const int row = g * BMQ + r;
        const float4* S4 = reinterpret_cast<const float4*>(
            g_S + (size_t)h * Nn * Nn + (size_t)row * Nn);

        float4 v0 = S4[t], v1 = S4[t + 256], v2 = S4[t + 512];
        float mx = fmaxf(fmaxf(fmaxf(v0.x, v0.y), fmaxf(v0.z, v0.w)),
                   fmaxf(fmaxf(fmaxf(v1.x, v1.y), fmaxf(v1.z, v1.w)),
                         fmaxf(fmaxf(v2.x, v2.y), fmaxf(v2.z, v2.w))));
#pragma unroll
        for (int o = 16; o > 0; o >>= 1) mx = fmaxf(mx, __shfl_xor_sync(0xffffffffu, mx, o));
        if (lane == 0) redm[warp] = mx;
        __syncthreads();
        float rowmax = redm[0];
#pragma unroll
        for (int w = 1; w < 8; w++) rowmax = fmaxf(rowmax, redm[w]);

        v0.x = expf(v0.x - rowmax); v0.y = expf(v0.y - rowmax);
        v0.z = expf(v0.z - rowmax); v0.w = expf(v0.w - rowmax);
        v1.x = expf(v1.x - rowmax); v1.y = expf(v1.y - rowmax);
        v1.z = expf(v1.z - rowmax); v1.w = expf(v1.w - rowmax);
        v2.x = expf(v2.x - rowmax); v2.y = expf(v2.y - rowmax);
        v2.z = expf(v2.z - rowmax); v2.w = expf(v2.w - rowmax);
        float sum = (v0.x + v0.y + v0.z + v0.w) + (v1.x + v1.y + v1.z + v1.w)
                  + (v2.x + v2.y + v2.z + v2.w);
#pragma unroll
        for (int o = 16; o > 0; o >>= 1) sum += __shfl_xor_sync(0xffffffffu, sum, o);
        if (lane == 0) reds[warp] = sum;
        __syncthreads();
        float tot = reds[0];
#pragma unroll
        for (int w = 1; w < 8; w++) tot += reds[w];
        const float inv = 1.f / tot;

        __nv_bfloat16* phr = g_ph + (size_t)h * Nn * Nn + (size_t)row * Nn;
        __nv_bfloat16* plr = g_pl + (size_t)h * Nn * Nn + (size_t)row * Nn;
        float4 vv[3] = {v0, v1, v2};
        int jj[3] = {t * 4, (t + 256) * 4, (t + 512) * 4};
#pragma unroll
        for (int s = 0; s < 3; s++) {
            float p0 = vv[s].x * inv, p1 = vv[s].y * inv,
                  p2 = vv[s].z * inv, p3 = vv[s].w * inv;
            int j = jj[s];
            colsum[j] += p0; colsum[j + 1] += p1; colsum[j + 2] += p2; colsum[j + 3] += p3;
            unsigned short h0 = __bfloat16_as_ushort(__float2bfloat16_rn(p0));
            unsigned short h1 = __bfloat16_as_ushort(__float2bfloat16_rn(p1));
            unsigned short h2 = __bfloat16_as_ushort(__float2bfloat16_rn(p2));
            unsigned short h3 = __bfloat16_as_ushort(__float2bfloat16_rn(p3));
            unsigned short l0 = __bfloat16_as_ushort(__float2bfloat16_rn(
                p0 - __bfloat162float(__ushort_as_bfloat16(h0))));
            unsigned short l1 = __bfloat16_as_ushort(__float2bfloat16_rn(
                p1 - __bfloat162float(__ushort_as_bfloat16(h1))));
            unsigned short l2 = __bfloat16_as_ushort(__float2bfloat16_rn(
                p2 - __bfloat162float(__ushort_as_bfloat16(h2))));
            unsigned short l3 = __bfloat16_as_ushort(__float2bfloat16_rn(
                p3 - __bfloat162float(__ushort_as_bfloat16(h3))));
            uint2 hw, lw;
            hw.x = (uint32_t)h0 | ((uint32_t)h1 << 16);
            hw.y = (uint32_t)h2 | ((uint32_t)h3 << 16);
            lw.x = (uint32_t)l0 | ((uint32_t)l1 << 16);
            lw.y = (uint32_t)l2 | ((uint32_t)l3 << 16);
            *reinterpret_cast<uint2*>(phr + j) = hw;
            *reinterpret_cast<uint2*>(plr + j) = lw;
        }
        __syncthreads();   // protect redm/reds for next row
    }

    float* cs = g_cs + (h * G + g) * Nn;
    for (int j = t; j < Nn; j += 256) atomicAdd(&cs[j], colsum[j]);
}

// =============================================================================
// K3: top-896 radix select + threefry random mask -> bitmask
// =============================================================================
__global__ __launch_bounds__(256) void select_kernel() {
    const int hg = blockIdx.x;
    const float* cs = g_cs + hg * Nn;
    const int t = threadIdx.x;

    __shared__ unsigned keys[Nn];
    __shared__ unsigned hist[256];
    __shared__ unsigned char mk[Nn];
    __shared__ unsigned sh_prefix, sh_need;

    for (int j = t; j < Nn; j += 256) {
        unsigned u = __float_as_uint(cs[j]);
        keys[j] = (u & 0x80000000u) ? ~u : (u | 0x80000000u);
        mk[j] = 0;
    }
    __syncthreads();

    unsigned prefix = 0, kneed = TOPK;
    for (int shift = 24; shift >= 0; shift -= 8) {
        hist[t] = 0;
        __syncthreads();
        const unsigned himask = (shift == 24) ? 0u : (0xFFFFFFFFu << (shift + 8));
        for (int j = t; j < Nn; j += 256) {
            unsigned u = keys[j];
            if (((u ^ prefix) & himask) == 0)
                atomicAdd(&hist[(u >> shift) & 255u], 1u);
        }
        __syncthreads();
        if (t == 0) {
            unsigned cum = 0; int b = 255;
            for (; b > 0; b--) {
                if (cum + hist[b] >= kneed) break;
                cum += hist[b];
            }
            sh_prefix = prefix | ((unsigned)b << shift);
            sh_need   = kneed - cum;
        }
        __syncthreads();
        prefix = sh_prefix; kneed = sh_need;
        __syncthreads();
    }
    const unsigned T = prefix;

    for (int j = t; j < Nn; j += 256)
        if (keys[j] > T) mk[j] = 1;
    __syncthreads();
    if (t == 0) {
        int need = (int)kneed;
        for (int j = 0; j < Nn && need > 0; j++)
            if (keys[j] == T) { mk[j] = 1; need--; }
    }
    __syncthreads();

    uint2 hk = tf2x32(0u, 1u, 0u, 0u);
    uint2 lk = tf2x32(0u, 1u, 0u, 1u);
    for (int j = t; j < Nn; j += 256) {
        unsigned f = (unsigned)(hg * Nn + j);
        unsigned hi = tf_bits32(hk.x, hk.y, f);
        unsigned lo = tf_bits32(lk.x, lk.y, f);
        unsigned off = ((hi % 100u) * 96u + (lo % 100u)) % 100u;
        if (off == 0u) mk[j] = 1;
    }
    __syncthreads();

    if (t < 96) {
        unsigned w = 0;
#pragma unroll
        for (int b = 0; b < 32; b++)
            if (mk[t * 32 + b]) w |= (1u << b);
        g_mask[hg * 96 + t] = w;
    }
}

// =============================================================================
// K4: fused PV — dense O, masked SP (smem masked planes, validated R11),
//     out2 = O - SP/den; 256 threads, 8 warps, warp tile 64(m) x 32(d)
//     smem planes: 0:Ph 1:Pl 2:Pmh 3:Pml 4:Vh 5:Vl  (+ masks + den)
// =============================================================================
__global__ __launch_bounds__(256) void pv_fused_kernel(float* __restrict__ out) {
    extern __shared__ char smem[];
    const uint32_t sb = smem_to_u32(smem);
    uint32_t* mskS = reinterpret_cast<uint32_t*>(smem + 6 * PLANE);   // [2][96]
    float*   den  = reinterpret_cast<float*>(smem + 6 * PLANE + 768); // [128]
    const int t = threadIdx.x, lane = t & 31, wid = t >> 5;
    const int h = blockIdx.z, bm = blockIdx.x * 128;

    const int ga = bm / BMQ;
    const int gb = (bm + 127) / BMQ;
    const int gbound = (ga + 1) * BMQ;
    if (t < 128) den[t] = 0.f;
    if (t >= 128 && t < 224) mskS[t - 128] = g_mask[(h * G + ga) * 96 + (t - 128)];
    if (t >= 224 && t < 256) {
        for (int w = t - 224; w < 96; w += 32)
            mskS[96 + w] = g_mask[(h * G + gb) * 96 + w];
    }
    __syncthreads();

    const __nv_bfloat16* ph = g_ph + (size_t)h * Nn * Nn + (size_t)bm * Nn;
    const __nv_bfloat16* pl = g_pl + (size_t)h * Nn * Nn + (size_t)bm * Nn;
    const __nv_bfloat16* vh = g_vth + (size_t)h * D * Nn;
    const __nv_bfloat16* vl = g_vtl + (size_t)h * D * Nn;

    const int m0 = (wid >> 2) * 64, n0 = (wid & 3) * 32;
    float accD[4][4][4], accM[4][4][4];
#pragma unroll
    for (int i = 0; i < 4; i++)
#pragma unroll
        for (int j = 0; j < 4; j++)
#pragma unroll
            for (int c = 0; c < 4; c++) { accD[i][j][c] = 0.f; accM[i][j][c] = 0.f; }

    for (int kc = 0; kc < 24; kc++) {
        if (kc) __syncthreads();
        for (int i = t; i < 2048; i += 256) {
            int row = i >> 4, c16 = i & 15;
            uint32_t o = sw_off(row, c16);
            const int colbase = kc * 128 + c16 * 8;
            const int gsel = ((bm + row) >= gbound) ? 1 : 0;
            const uint32_t mbits = mskS[gsel * 96 + (colbase >> 5)] >> (colbase & 31);

            size_t goff = (size_t)row * Nn + colbase;
            uint4 hq = *reinterpret_cast<const uint4*>(ph + goff);
            uint4 lq = *reinterpret_cast<const uint4*>(pl + goff);
            *reinterpret_cast<uint4*>(smem + o) = hq;
            *reinterpret_cast<uint4*>(smem + PLANE + o) = lq;

            // masked planes: AND with per-halfword select (bf16 0x0000 == +0)
            uint32_t s0 = ((mbits & 1u) ? 0xFFFFu : 0u) | ((mbits & 2u) ? 0xFFFF0000u : 0u);
            uint32_t s1 = ((mbits & 4u) ? 0xFFFFu : 0u) | ((mbits & 8u) ? 0xFFFF0000u : 0u);
            uint32_t s2 = ((mbits & 16u) ? 0xFFFFu : 0u) | ((mbits & 32u) ? 0xFFFF0000u : 0u);
            uint32_t s3 = ((mbits & 64u) ? 0xFFFFu : 0u) | ((mbits & 128u) ? 0xFFFF0000u : 0u);
            uint4 mh = make_uint4(hq.x & s0, hq.y & s1, hq.z & s2, hq.w & s3);
            uint4 ml = make_uint4(lq.x & s0, lq.y & s1, lq.z & s2, lq.w & s3);
            *reinterpret_cast<uint4*>(smem + 2 * PLANE + o) = mh;
            *reinterpret_cast<uint4*>(smem + 3 * PLANE + o) = ml;

            if (mbits & 0xFFu) {
                float2 a0 = __bfloat1622float2(*reinterpret_cast<__nv_bfloat162*>(&mh.x));
                float2 a1 = __bfloat1622float2(*reinterpret_cast<__nv_bfloat162*>(&mh.y));
                float2 a2 = __bfloat1622float2(*reinterpret_cast<__nv_bfloat162*>(&mh.z));
                float2 a3 = __bfloat1622float2(*reinterpret_cast<__nv_bfloat162*>(&mh.w));
                float2 b0 = __bfloat1622float2(*reinterpret_cast<__nv_bfloat162*>(&ml.x));
                float2 b1 = __bfloat1622float2(*reinterpret_cast<__nv_bfloat162*>(&ml.y));
                float2 b2 = __bfloat1622float2(*reinterpret_cast<__nv_bfloat162*>(&ml.z));
                float2 b3 = __bfloat1622float2(*reinterpret_cast<__nv_bfloat162*>(&ml.w));
                float dsum = (a0.x + a0.y + a1.x + a1.y + a2.x + a2.y + a3.x + a3.y)
                           + (b0.x + b0.y + b1.x + b1.y + b2.x + b2.y + b3.x + b3.y);
                atomicAdd(&den[row], dsum);
            }

            *reinterpret_cast<uint4*>(smem + 4 * PLANE + o) = *reinterpret_cast<const uint4*>(vh + goff);
            *reinterpret_cast<uint4*>(smem + 5 * PLANE + o) = *reinterpret_cast<const uint4*>(vl + goff);
        }
        __syncthreads();

#pragma unroll
        for (int kk = 0; kk < 8; kk++) {
            const int arow = (lane & 15), ach = kk * 2 + (lane >> 4);
            uint32_t Bh[4][2], Bl[4][2];
#pragma unroll
            for (int nj = 0; nj < 2; nj++) {
                int row = n0 + nj * 16 + arow;
                uint32_t r0, r1, r2, r3;
                ldsm_x4(r0, r1, r2, r3, sb + 4 * PLANE + sw_off(row, ach));
                Bh[nj * 2][0] = r0; Bh[nj * 2][1] = r2;
                Bh[nj * 2 + 1][0] = r1; Bh[nj * 2 + 1][1] = r3;
                ldsm_x4(r0, r1, r2, r3, sb + 5 * PLANE + sw_off(row, ach));
                Bl[nj * 2][0] = r0; Bl[nj * 2][1] = r2;
                Bl[nj * 2 + 1][0] = r1; Bl[nj * 2 + 1][1] = r3;
            }
#pragma unroll
            for (int mi = 0; mi < 4; mi++) {
                int row = m0 + mi * 16 + arow;
                uint32_t Ah[4], Al[4], Amh[4], Aml[4];
                ldsm_x4(Ah[0], Ah[1], Ah[2], Ah[3], sb + sw_off(row, ach));
                ldsm_x4(Al[0], Al[1], Al[2], Al[3], sb + PLANE + sw_off(row, ach));
                ldsm_x4(Amh[0], Amh[1], Amh[2], Amh[3], sb + 2 * PLANE + sw_off(row, ach));
                ldsm_x4(Aml[0], Aml[1], Aml[2], Aml[3], sb + 3 * PLANE + sw_off(row, ach));
#pragma unroll
                for (int n8 = 0; n8 < 4; n8++) {
                    mma_bf16(accD[mi][n8], Ah, Bh[n8]);
                    mma_bf16(accD[mi][n8], Al, Bh[n8]);
                    mma_bf16(accD[mi][n8], Ah, Bl[n8]);
                    mma_bf16(accM[mi][n8], Amh, Bh[n8]);
                    mma_bf16(accM[mi][n8], Aml, Bh[n8]);
                    mma_bf16(accM[mi][n8], Amh, Bl[n8]);
                }
            }
        }
    }
    __syncthreads();

    float* O  = out + (size_t)h * Nn * D;
    float* O2 = out + (size_t)H * Nn * D + (size_t)h * Nn * D;
#pragma unroll
    for (int mi = 0; mi < 4; mi++) {
#pragma unroll
        for (int n8 = 0; n8 < 4; n8++) {
            int rl0 = m0 + mi * 16 + (lane >> 2);
            int rl1 = rl0 + 8;
            int c = n0 + n8 * 8 + (lane & 3) * 2;
            float inv0 = 1.f / den[rl0];
            float inv1 = 1.f / den[rl1];
            float2 d01 = make_float2(accD[mi][n8][0], accD[mi][n8][1]);
            float2 d23 = make_float2(accD[mi][n8][2], accD[mi][n8][3]);
            *reinterpret_cast<float2*>(&O[(size_t)(bm + rl0) * D + c]) = d01;
            *reinterpret_cast<float2*>(&O[(size_t)(bm + rl1) * D + c]) = d23;
            float2 s01 = make_float2(d01.x - accM[mi][n8][0] * inv0,
                                     d01.y - accM[mi][n8][1] * inv0);
            float2 s23 = make_float2(d23.x - accM[mi][n8][2] * inv1,
                                     d23.y - accM[mi][n8][3] * inv1);
            *reinterpret_cast<float2*>(&O2[(size_t)(bm + rl0) * D + c]) = s01;
            *reinterpret_cast<float2*>(&O2[(size_t)(bm + rl1) * D + c]) = s23;
        }
    }
}

// =============================================================================
extern "C" void kernel_launch(void* const* d_in, const int* in_sizes, int n_in,
                              void* d_out, int out_size) {
    const float* q = (const float*)d_in[0];
    const float* k = (const float*)d_in[1];
    const float* v = (const float*)d_in[2];
    float* out = (float*)d_out;

    const int SMEM_QK = 6 * PLANE;             // 192 KB
    const int SMEM_PV = 6 * PLANE + 768 + 512; // 192 KB + masks + den
    cudaFuncSetAttribute(qk_mma_kernel, cudaFuncAttributeMaxDynamicSharedMemorySize, SMEM_QK);
    cudaFuncSetAttribute(pv_fused_kernel, cudaFuncAttributeMaxDynamicSharedMemorySize, SMEM_PV);

    split_qk_kernel<<<dim3(9216, 2), 256>>>(q, k);
    vtrans_kernel<<<dim3(Nn / 32, D / 32, H), dim3(32, 8)>>>(v);
    qk_mma_kernel<<<dim3(24, 24, H), 256, SMEM_QK>>>();
    softmax_cs_kernel<<<dim3(4 * G, H), 256>>>();
    select_kernel<<<HG, 256>>>();
    pv_fused_kernel<<<dim3(24, 1, H), 256, SMEM_PV>>>(out);
}